// round 10
// baseline (speedup 1.0000x reference)
#include <cuda_runtime.h>
#include <math.h>

#define Bb 2
#define Tt 16
#define Hh 64
#define Ww 64
#define Cc 64

typedef unsigned long long ull;

// Scratch (static device globals: allowed; no cudaMalloc anywhere)
__device__ float2 g_Y[Bb*Tt*Hh*Ww*Cc];      // 134 MB working complex field
// Pair-packed kernel-DFT tables, 16B per (t,h,c) record -> coalesced LDG.128:
//   g_G2m = {mA, mB}, g_G2s = {sA, sB}, g_G2d = {dAsw, dBsw}
// where dXsw = (d.y, -d.x) pre-swapped for FFMA2 synthesis.
__device__ __align__(16) ulonglong2 g_G2m[Tt*Hh*Cc];
__device__ __align__(16) ulonglong2 g_G2s[Tt*Hh*Cc];
__device__ __align__(16) ulonglong2 g_G2d[Tt*Hh*Cc];

// ---------------- f32x2 packed helpers (sm_103a FFMA2 path) ----------------
__device__ __forceinline__ ull PK2(float x, float y){
    ull r; asm("mov.b64 %0, {%1,%2};" : "=l"(r) : "f"(x), "f"(y)); return r;
}
__device__ __forceinline__ float2 UPK2(ull p){
    float x, y; asm("mov.b64 {%0,%1}, %2;" : "=f"(x), "=f"(y) : "l"(p));
    return make_float2(x, y);
}
__device__ __forceinline__ ull FMA2v(ull a, ull b, ull c){
    ull r; asm("fma.rn.f32x2 %0, %1, %2, %3;" : "=l"(r) : "l"(a), "l"(b), "l"(c));
    return r;
}

__device__ __forceinline__ float2 cmul(float2 a, float2 b){
    return make_float2(fmaf(a.x, b.x, -a.y*b.y), fmaf(a.x, b.y, a.y*b.x));
}
__device__ __forceinline__ float2 cadd(float2 a, float2 b){
    return make_float2(a.x + b.x, a.y + b.y);
}
__device__ __forceinline__ float2 csub(float2 a, float2 b){
    return make_float2(a.x - b.x, a.y - b.y);
}

// exp(S * 2*pi*i * m / 16) as compile-time constants
#define C16_1 0.92387953251128675613f
#define C16_2 0.70710678118654752440f
#define C16_3 0.38268343236508977173f
__device__ __forceinline__ float2 w16c(int m, float S){
    switch(m){
        default: return make_float2( 1.f, 0.f);
        case 1:  return make_float2( C16_1,  S*C16_3);
        case 2:  return make_float2( C16_2,  S*C16_2);
        case 3:  return make_float2( C16_3,  S*C16_1);
        case 4:  return make_float2( 0.f,    S);
        case 5:  return make_float2(-C16_3,  S*C16_1);
        case 6:  return make_float2(-C16_2,  S*C16_2);
        case 7:  return make_float2(-C16_1,  S*C16_3);
        case 8:  return make_float2(-1.f,    0.f);
        case 9:  return make_float2(-C16_1, -S*C16_3);
    }
}
__device__ __forceinline__ float2 cmulW(float2 a, int m, float S){
    if(m == 0) return a;
    return cmul(a, w16c(m, S));
}

// 4-point butterfly, in place. SIGN=-1 forward, +1 inverse.
template<int SIGN>
__device__ __forceinline__ void b4(float2& x0, float2& x1, float2& x2, float2& x3){
    const float S = (float)SIGN;
    float2 e=cadd(x0,x2), f=csub(x0,x2);
    float2 g=cadd(x1,x3), h=csub(x1,x3);
    float2 ih=make_float2(-S*h.y, S*h.x);     // S*i*h
    x0=cadd(e,g); x1=cadd(f,ih); x2=csub(e,g); x3=csub(f,ih);
}

// In-place DIF radix-4 FFT16, natural input -> digit-swapped output:
// slot m = 4q+j holds bin k = q+4j.  SIGN=-1 (forward).
template<int SIGN>
__device__ __forceinline__ void fft16_fwd_ip(float2* v){
    const float S = (float)SIGN;
#pragma unroll
    for(int i=0;i<4;i++){
        b4<SIGN>(v[i], v[i+4], v[i+8], v[i+12]);
        v[i+4]  = cmulW(v[i+4],    i, S);
        v[i+8]  = cmulW(v[i+8],  2*i, S);
        v[i+12] = cmulW(v[i+12], 3*i, S);
    }
#pragma unroll
    for(int q=0;q<4;q++) b4<SIGN>(v[4*q], v[4*q+1], v[4*q+2], v[4*q+3]);
}

// In-place DIT radix-4 IFFT16, digit-swapped input -> natural output.
template<int SIGN>
__device__ __forceinline__ void fft16_inv_ip(float2* v){
    const float S = (float)SIGN;
#pragma unroll
    for(int q=0;q<4;q++){
        b4<SIGN>(v[4*q], v[4*q+1], v[4*q+2], v[4*q+3]);
        v[4*q+1] = cmulW(v[4*q+1],   q, S);
        v[4*q+2] = cmulW(v[4*q+2], 2*q, S);
        v[4*q+3] = cmulW(v[4*q+3], 3*q, S);
    }
#pragma unroll
    for(int i=0;i<4;i++) b4<SIGN>(v[i], v[i+4], v[i+8], v[i+12]);
}

// Naive 8-point DFT in registers. SIGN=-1 forward, +1 inverse (no scaling).
template<int SIGN>
__device__ __forceinline__ void dft8(const float2* in, float2* out){
    const float R = 0.70710678118654752f;
    const float S = (float)SIGN;
    float2 w[8];
    w[0] = make_float2( 1.f,  0.f);
    w[1] = make_float2(  R,  S*R);
    w[2] = make_float2( 0.f,  S);
    w[3] = make_float2( -R,  S*R);
    w[4] = make_float2(-1.f,  0.f);
    w[5] = make_float2( -R, -S*R);
    w[6] = make_float2( 0.f, -S);
    w[7] = make_float2(  R, -S*R);
#pragma unroll
    for(int k=0;k<8;k++){
        float2 acc = in[0];
#pragma unroll
        for(int n=1;n<8;n++){
            acc = cadd(acc, cmul(in[n], w[(n*k)&7]));
        }
        out[k] = acc;
    }
}

// ---------------------------------------------------------------------------
// Pass 0: separable DFT of the 3x3x3 kernels over (T,H) axes -> pair tables.
// ---------------------------------------------------------------------------
__global__ void build_g2_kernel(const float* __restrict__ Ak,
                                const float* __restrict__ Bk){
    int c = threadIdx.x;            // 64
    int t = blockIdx.x >> 6;        // grid = Tt*Hh = 1024
    int h = blockIdx.x & 63;
    float s_, c_;
    float2 ET[3], EH[3];
    sincospif(2.0f*(float)t/16.0f, &s_, &c_);
    ET[0] = make_float2(c_,  s_);
    ET[1] = make_float2(1.f, 0.f);
    ET[2] = make_float2(c_, -s_);
    sincospif(2.0f*(float)h/64.0f, &s_, &c_);
    EH[0] = make_float2(c_,  s_);
    EH[1] = make_float2(1.f, 0.f);
    EH[2] = make_float2(c_, -s_);
    float2 vA[3], vB[3];
#pragma unroll
    for(int k=0;k<3;k++){
        float2 aA = make_float2(0.f,0.f), aB = make_float2(0.f,0.f);
#pragma unroll
        for(int i=0;i<3;i++){
#pragma unroll
            for(int j=0;j<3;j++){
                float2 e = cmul(ET[i], EH[j]);
                float va = Ak[c*27 + i*9 + j*3 + k];
                float vb = Bk[c*27 + i*9 + j*3 + k];
                aA.x = fmaf(va, e.x, aA.x); aA.y = fmaf(va, e.y, aA.y);
                aB.x = fmaf(vb, e.x, aB.x); aB.y = fmaf(vb, e.y, aB.y);
            }
        }
        vA[k] = aA; vB[k] = aB;
    }
    float2 sA = cadd(vA[0], vA[2]), dA = csub(vA[0], vA[2]);
    float2 sB = cadd(vB[0], vB[2]), dB = csub(vB[0], vB[2]);
    int idx = (t*64 + h)*64 + c;
    g_G2m[idx] = make_ulonglong2(PK2(vA[1].x, vA[1].y), PK2(vB[1].x, vB[1].y));
    g_G2s[idx] = make_ulonglong2(PK2(sA.x, sA.y),       PK2(sB.x, sB.y));
    g_G2d[idx] = make_ulonglong2(PK2(dA.y, -dA.x),      PK2(dB.y, -dB.x));
}

// ---------------------------------------------------------------------------
// Pass 1: forward FFT along W (length 64 = 8x8), real input -> g_Y complex.
// ---------------------------------------------------------------------------
__global__ void __launch_bounds__(512) fftW_fwd_kernel(const float* __restrict__ x){
    __shared__ float2 sh[8][8][64];     // [n1][k2][c]
    int c = threadIdx.x & 63;
    int r = threadIdx.x >> 6;
    size_t line = blockIdx.x;           // (b*T+t)*H + h
    const float* xp = x + line*(size_t)(Ww*Cc) + c;
    float2 v[8], o[8];
#pragma unroll
    for(int n2=0;n2<8;n2++) v[n2] = make_float2(xp[(r + 8*n2)*Cc], 0.f);
    dft8<-1>(v, o);
    float s_, c_;
    sincospif(-(float)r/32.0f, &s_, &c_);
    float2 wr = make_float2(c_, s_);
    float2 wcur = make_float2(1.f, 0.f);
#pragma unroll
    for(int k2=0;k2<8;k2++){
        sh[r][k2][c] = cmul(o[k2], wcur);
        wcur = cmul(wcur, wr);
    }
    __syncthreads();
#pragma unroll
    for(int n1=0;n1<8;n1++) v[n1] = sh[n1][r][c];
    dft8<-1>(v, o);
    float2* yp = g_Y + line*(size_t)(Ww*Cc) + c;
#pragma unroll
    for(int k1=0;k1<8;k1++) yp[(r + 8*k1)*Cc] = o[k1];
}

// ---------------------------------------------------------------------------
// Passes 2/4: FFT along H (length 64), complex, in-place in g_Y.
// ---------------------------------------------------------------------------
template<int SIGN>
__global__ void __launch_bounds__(512) fftH_kernel(){
    __shared__ float2 sh[8][8][64];
    int c = threadIdx.x & 63;
    int r = threadIdx.x >> 6;
    int line = blockIdx.x;              // (b*T+t)*W + w
    int bt = line >> 6;
    int w  = line & 63;
    float2* yp = g_Y + (size_t)bt*(Hh*Ww*Cc) + (size_t)w*Cc + c;
    float2 v[8], o[8];
#pragma unroll
    for(int n2=0;n2<8;n2++) v[n2] = yp[(size_t)(r + 8*n2)*(Ww*Cc)];
    dft8<SIGN>(v, o);
    float s_, c_;
    sincospif((float)SIGN*(float)r/32.0f, &s_, &c_);
    float2 wr = make_float2(c_, s_);
    float2 wcur = make_float2(1.f, 0.f);
#pragma unroll
    for(int k2=0;k2<8;k2++){
        sh[r][k2][c] = cmul(o[k2], wcur);
        wcur = cmul(wcur, wr);
    }
    __syncthreads();
#pragma unroll
    for(int n1=0;n1<8;n1++) v[n1] = sh[n1][r][c];
    dft8<SIGN>(v, o);
#pragma unroll
    for(int k1=0;k1<8;k1++) yp[(size_t)(r + 8*k1)*(Ww*Cc)] = o[k1];
}

// ---------------------------------------------------------------------------
// Pass 3 (fused): forward FFT16(T) + gates + A_f/B_f synthesis + scan +
// inverse FFT16(T). Block = 256 threads = 4 w x 64 c; grid = B*H*(W/4).
// Shared pool (48 KB static):
//   [0 .. 16384)      sxp[p][c2][j] ull: x packed over t-pairs
//   [16384 .. 49152)  sW2[c2][c]    ull: delta_W duplicated pairs
//   [16384 .. 49152)  overlay after matvec barrier: sg2[p][t][c] float2 {fgt,gt}
// ---------------------------------------------------------------------------
__global__ void __launch_bounds__(256, 3) scan_kernel(
    const float* __restrict__ x,
    const float* __restrict__ fb,  const float* __restrict__ fs,
    const float* __restrict__ ibv, const float* __restrict__ isc,
    const float* __restrict__ dW,  const float* __restrict__ db)
{
    __shared__ __align__(16) char pool[49152];
    ull*    sxp = (ull*)pool;                   // [p*512 + c2*8 + j]
    ull*    sW2 = (ull*)(pool + 16384);         // [c2*64 + c]
    float2* sg2 = (float2*)(pool + 16384);      // overlay: [p*1024 + t*64 + c]

    int tid = threadIdx.x;
    int c = tid & 63;
    int p = tid >> 6;
    int bi = blockIdx.x;
    int b  = bi >> 10;              // 1024 = Hh * (Ww/4)
    int h  = (bi >> 4) & 63;
    int w4 = bi & 15;
    int w  = w4*4 + p;

    // delta_W is [c2][d] row-major; duplicate each scalar into a f32x2 pair
#pragma unroll
    for(int k=0;k<16;k++){
        int i = tid + k*256;
        float wv = dW[i];
        sW2[i] = PK2(wv, wv);       // lanes contiguous -> conflict-free STS.64
    }
    // x tile staged as packed t-pairs: sxp[p][c2][j] = (x[2j][c2], x[2j+1][c2])
    size_t xbase = (size_t)b*(Tt*Hh*Ww*Cc) + (size_t)h*(Ww*Cc) + (size_t)(w4*4)*Cc;
    {
        ull* dst = sxp + p*512 + c*8;
#pragma unroll
        for(int j=0;j<8;j++){
            float a0 = x[xbase + (size_t)(2*j  )*(Hh*Ww*Cc) + tid];
            float a1 = x[xbase + (size_t)(2*j+1)*(Hh*Ww*Cc) + tid];
            dst[j] = PK2(a0, a1);
        }
    }
    __syncthreads();

    // packed matvec: dotp[j] = (dot[2j], dot[2j+1]); c2 accumulated in order
    // (identical fp32 accumulation order to the scalar version).
    ull dotp[8];
    {
        float dbc = db[c];
        ull dbp = PK2(dbc, dbc);
#pragma unroll
        for(int j=0;j<8;j++) dotp[j] = dbp;
        const ull* xrow = sxp + p*512;
#pragma unroll
        for(int c2=0; c2<64; c2+=2){
            ull w0 = sW2[ c2   *64 + c];          // LDS.64, lanes contiguous
            ull w1 = sW2[(c2+1)*64 + c];
            const ull* base0 = xrow +  c2   *8;   // j=0..7 pairs for c2
            const ull* base1 = xrow + (c2+1)*8;   // j=0..7 pairs for c2+1
#pragma unroll
            for(int jj=0;jj<4;jj++){
                ulonglong2 x0 = *(const ulonglong2*)&base0[jj*2];  // LDS.128 bcast
                ulonglong2 x1 = *(const ulonglong2*)&base1[jj*2];
                dotp[2*jj  ] = FMA2v(x0.x, w0, dotp[2*jj  ]);
                dotp[2*jj+1] = FMA2v(x0.y, w0, dotp[2*jj+1]);
                dotp[2*jj  ] = FMA2v(x1.x, w1, dotp[2*jj  ]);
                dotp[2*jj+1] = FMA2v(x1.y, w1, dotp[2*jj+1]);
            }
        }
    }

    // gates into registers (reads own sxp slots), then barrier, then store
    float gf[16], gg[16];
    {
        float fbc = fb[c], fsc = fs[c], ibc = ibv[c], iscv = isc[c];
        const ull* own = sxp + p*512 + c*8;
#pragma unroll
        for(int j=0;j<8;j++){
            float2 xp2 = UPK2(own[j]);
            float2 dp  = UPK2(dotp[j]);
#pragma unroll
            for(int u=0;u<2;u++){
                float xv = u ? xp2.y : xp2.x;
                float d  = u ? dp.y  : dp.x;
                float fgt = __fdividef(1.f, 1.f + __expf(-(fbc + fsc*xv)));
                float igt = __fdividef(1.f, 1.f + __expf(-(ibc + iscv*xv)));
                float spv = fmaxf(d, 0.f) + __logf(1.f + __expf(-fabsf(d)));
                gf[2*j+u] = fgt;
                gg[2*j+u] = igt * spv;
            }
        }
    }
    __syncthreads();   // all sW2/sxp matvec reads done; safe to overlay sg2
#pragma unroll
    for(int t=0;t<16;t++){
        sg2[p*1024 + t*64 + c] = make_float2(gf[t], gg[t]);
    }

    // load T-line of (H,W)-transformed data; forward FFT along T in place
    size_t ybase = (size_t)b*(Tt*Hh*Ww*Cc) + (size_t)h*(Ww*Cc) + (size_t)w*Cc + c;
    float2 v[16];
#pragma unroll
    for(int t=0;t<16;t++) v[t] = g_Y[ybase + (size_t)t*(Hh*Ww*Cc)];
    fft16_fwd_ip<-1>(v);     // slot 4q+j = bin q+4j

    // E = exp(-2pi i w/64); packed synthesis with pre-swapped diff tables:
    // Af = FMA2(dsw, ey2, FMA2(s, ex2, m))
    float ey, ex;
    sincospif(-(float)w/32.0f, &ey, &ex);
    ull ex2 = PK2(ex, ex), ey2 = PK2(ey, ey);

    float2 hp = make_float2(0.f, 0.f);
#pragma unroll
    for(int t=0;t<16;t++){
        const int sl = 4*(t&3) + (t>>2);     // digit-swapped slot of bin t
        float2 gv = sg2[p*1024 + t*64 + c];  // {fgt, gt}

        int gi = (t*64 + h)*64 + c;
        ulonglong2 m2 = g_G2m[gi];           // {mA, mB}  coalesced LDG.128
        ulonglong2 s2 = g_G2s[gi];           // {sA, sB}
        ulonglong2 d2 = g_G2d[gi];           // {dAsw, dBsw}
        float2 Af = UPK2(FMA2v(d2.x, ey2, FMA2v(s2.x, ex2, m2.x)));
        float2 Bf = UPK2(FMA2v(d2.y, ey2, FMA2v(s2.y, ex2, m2.y)));

        float2 at = make_float2(gv.x*Af.x, gv.x*Af.y);
        float2 bt = cmul(Bf, v[sl]);
        bt.x *= gv.y; bt.y *= gv.y;
        hp = cadd(cmul(at, hp), bt);          // h[t] = a*h[t-1] + b
        v[sl] = hp;
    }

    fft16_inv_ip<1>(v);                        // digit-swapped in -> natural out
#pragma unroll
    for(int t=0;t<16;t++){
        g_Y[ybase + (size_t)t*(Hh*Ww*Cc)] = v[t];
    }
}

// ---------------------------------------------------------------------------
// Pass 5: inverse FFT along W, write real part * 1/(T*H*W) to output.
// ---------------------------------------------------------------------------
__global__ void __launch_bounds__(512) ifftW_real_kernel(float* __restrict__ out){
    __shared__ float2 sh[8][8][64];
    int c = threadIdx.x & 63;
    int r = threadIdx.x >> 6;
    size_t line = blockIdx.x;
    const float2* yp = g_Y + line*(size_t)(Ww*Cc) + c;
    float2 v[8], o[8];
#pragma unroll
    for(int n2=0;n2<8;n2++) v[n2] = yp[(size_t)(r + 8*n2)*Cc];
    dft8<1>(v, o);
    float s_, c_;
    sincospif((float)r/32.0f, &s_, &c_);
    float2 wr = make_float2(c_, s_);
    float2 wcur = make_float2(1.f, 0.f);
#pragma unroll
    for(int k2=0;k2<8;k2++){
        sh[r][k2][c] = cmul(o[k2], wcur);
        wcur = cmul(wcur, wr);
    }
    __syncthreads();
#pragma unroll
    for(int n1=0;n1<8;n1++) v[n1] = sh[n1][r][c];
    dft8<1>(v, o);
    float* op = out + line*(size_t)(Ww*Cc) + c;
    const float sc = 1.0f/65536.0f;          // 1/(T*H*W)
#pragma unroll
    for(int k1=0;k1<8;k1++) op[(r + 8*k1)*Cc] = o[k1].x * sc;
}

// ---------------------------------------------------------------------------
extern "C" void kernel_launch(void* const* d_in, const int* in_sizes, int n_in,
                              void* d_out, int out_size){
    const float* x   = (const float*)d_in[0];
    const float* Ak  = (const float*)d_in[1];
    const float* Bk  = (const float*)d_in[2];
    const float* fb  = (const float*)d_in[3];
    const float* fs  = (const float*)d_in[4];
    const float* ib  = (const float*)d_in[5];
    const float* isc = (const float*)d_in[6];
    const float* dW  = (const float*)d_in[7];
    const float* db  = (const float*)d_in[8];
    float* out = (float*)d_out;

    build_g2_kernel<<<Tt*Hh, 64>>>(Ak, Bk);
    fftW_fwd_kernel<<<Bb*Tt*Hh, 512>>>(x);
    fftH_kernel<-1><<<Bb*Tt*Ww, 512>>>();
    scan_kernel<<<Bb*Hh*(Ww/4), 256>>>(x, fb, fs, ib, isc, dW, db);
    fftH_kernel<1><<<Bb*Tt*Ww, 512>>>();
    ifftW_real_kernel<<<Bb*Tt*Hh, 512>>>(out);
}

// round 11
// speedup vs baseline: 1.0973x; 1.0973x over previous
#include <cuda_runtime.h>
#include <math.h>

#define Bb 2
#define Tt 16
#define Hh 64
#define Ww 64
#define Cc 64

typedef unsigned long long ull;

// Scratch (static device globals: allowed; no cudaMalloc anywhere)
__device__ float2 g_Y[Bb*Tt*Hh*Ww*Cc];      // 67 MB working complex field
__device__ float2 g_G[Bb*Tt*Hh*Ww*Cc];      // 67 MB gate buffer {fgt, gt}
// Pair-packed kernel-DFT tables, 16B per (t,h,c) record -> coalesced LDG.128:
//   g_G2m = {mA, mB}, g_G2s = {sA, sB}, g_G2d = {dAsw, dBsw}
// where dXsw = (d.y, -d.x) pre-swapped for FFMA2 synthesis.
__device__ __align__(16) ulonglong2 g_G2m[Tt*Hh*Cc];
__device__ __align__(16) ulonglong2 g_G2s[Tt*Hh*Cc];
__device__ __align__(16) ulonglong2 g_G2d[Tt*Hh*Cc];

// ---------------- f32x2 packed helpers (sm_103a FFMA2 path) ----------------
__device__ __forceinline__ ull PK2(float x, float y){
    ull r; asm("mov.b64 %0, {%1,%2};" : "=l"(r) : "f"(x), "f"(y)); return r;
}
__device__ __forceinline__ float2 UPK2(ull p){
    float x, y; asm("mov.b64 {%0,%1}, %2;" : "=f"(x), "=f"(y) : "l"(p));
    return make_float2(x, y);
}
__device__ __forceinline__ ull FMA2v(ull a, ull b, ull c){
    ull r; asm("fma.rn.f32x2 %0, %1, %2, %3;" : "=l"(r) : "l"(a), "l"(b), "l"(c));
    return r;
}

__device__ __forceinline__ float2 cmul(float2 a, float2 b){
    return make_float2(fmaf(a.x, b.x, -a.y*b.y), fmaf(a.x, b.y, a.y*b.x));
}
__device__ __forceinline__ float2 cadd(float2 a, float2 b){
    return make_float2(a.x + b.x, a.y + b.y);
}
__device__ __forceinline__ float2 csub(float2 a, float2 b){
    return make_float2(a.x - b.x, a.y - b.y);
}

// exp(S * 2*pi*i * m / 16) as compile-time constants
#define C16_1 0.92387953251128675613f
#define C16_2 0.70710678118654752440f
#define C16_3 0.38268343236508977173f
__device__ __forceinline__ float2 w16c(int m, float S){
    switch(m){
        default: return make_float2( 1.f, 0.f);
        case 1:  return make_float2( C16_1,  S*C16_3);
        case 2:  return make_float2( C16_2,  S*C16_2);
        case 3:  return make_float2( C16_3,  S*C16_1);
        case 4:  return make_float2( 0.f,    S);
        case 5:  return make_float2(-C16_3,  S*C16_1);
        case 6:  return make_float2(-C16_2,  S*C16_2);
        case 7:  return make_float2(-C16_1,  S*C16_3);
        case 8:  return make_float2(-1.f,    0.f);
        case 9:  return make_float2(-C16_1, -S*C16_3);
    }
}
__device__ __forceinline__ float2 cmulW(float2 a, int m, float S){
    if(m == 0) return a;
    return cmul(a, w16c(m, S));
}

// 4-point butterfly, in place. SIGN=-1 forward, +1 inverse.
template<int SIGN>
__device__ __forceinline__ void b4(float2& x0, float2& x1, float2& x2, float2& x3){
    const float S = (float)SIGN;
    float2 e=cadd(x0,x2), f=csub(x0,x2);
    float2 g=cadd(x1,x3), h=csub(x1,x3);
    float2 ih=make_float2(-S*h.y, S*h.x);     // S*i*h
    x0=cadd(e,g); x1=cadd(f,ih); x2=csub(e,g); x3=csub(f,ih);
}

// In-place DIF radix-4 FFT16, natural input -> digit-swapped output:
// slot m = 4q+j holds bin k = q+4j.  SIGN=-1 (forward).
template<int SIGN>
__device__ __forceinline__ void fft16_fwd_ip(float2* v){
    const float S = (float)SIGN;
#pragma unroll
    for(int i=0;i<4;i++){
        b4<SIGN>(v[i], v[i+4], v[i+8], v[i+12]);
        v[i+4]  = cmulW(v[i+4],    i, S);
        v[i+8]  = cmulW(v[i+8],  2*i, S);
        v[i+12] = cmulW(v[i+12], 3*i, S);
    }
#pragma unroll
    for(int q=0;q<4;q++) b4<SIGN>(v[4*q], v[4*q+1], v[4*q+2], v[4*q+3]);
}

// In-place DIT radix-4 IFFT16, digit-swapped input -> natural output.
template<int SIGN>
__device__ __forceinline__ void fft16_inv_ip(float2* v){
    const float S = (float)SIGN;
#pragma unroll
    for(int q=0;q<4;q++){
        b4<SIGN>(v[4*q], v[4*q+1], v[4*q+2], v[4*q+3]);
        v[4*q+1] = cmulW(v[4*q+1],   q, S);
        v[4*q+2] = cmulW(v[4*q+2], 2*q, S);
        v[4*q+3] = cmulW(v[4*q+3], 3*q, S);
    }
#pragma unroll
    for(int i=0;i<4;i++) b4<SIGN>(v[i], v[i+4], v[i+8], v[i+12]);
}

// Naive 8-point DFT in registers. SIGN=-1 forward, +1 inverse (no scaling).
template<int SIGN>
__device__ __forceinline__ void dft8(const float2* in, float2* out){
    const float R = 0.70710678118654752f;
    const float S = (float)SIGN;
    float2 w[8];
    w[0] = make_float2( 1.f,  0.f);
    w[1] = make_float2(  R,  S*R);
    w[2] = make_float2( 0.f,  S);
    w[3] = make_float2( -R,  S*R);
    w[4] = make_float2(-1.f,  0.f);
    w[5] = make_float2( -R, -S*R);
    w[6] = make_float2( 0.f, -S);
    w[7] = make_float2(  R, -S*R);
#pragma unroll
    for(int k=0;k<8;k++){
        float2 acc = in[0];
#pragma unroll
        for(int n=1;n<8;n++){
            acc = cadd(acc, cmul(in[n], w[(n*k)&7]));
        }
        out[k] = acc;
    }
}

// ---------------------------------------------------------------------------
// Pass 0: separable DFT of the 3x3x3 kernels over (T,H) axes -> pair tables.
// ---------------------------------------------------------------------------
__global__ void build_g2_kernel(const float* __restrict__ Ak,
                                const float* __restrict__ Bk){
    int c = threadIdx.x;            // 64
    int t = blockIdx.x >> 6;        // grid = Tt*Hh = 1024
    int h = blockIdx.x & 63;
    float s_, c_;
    float2 ET[3], EH[3];
    sincospif(2.0f*(float)t/16.0f, &s_, &c_);
    ET[0] = make_float2(c_,  s_);
    ET[1] = make_float2(1.f, 0.f);
    ET[2] = make_float2(c_, -s_);
    sincospif(2.0f*(float)h/64.0f, &s_, &c_);
    EH[0] = make_float2(c_,  s_);
    EH[1] = make_float2(1.f, 0.f);
    EH[2] = make_float2(c_, -s_);
    float2 vA[3], vB[3];
#pragma unroll
    for(int k=0;k<3;k++){
        float2 aA = make_float2(0.f,0.f), aB = make_float2(0.f,0.f);
#pragma unroll
        for(int i=0;i<3;i++){
#pragma unroll
            for(int j=0;j<3;j++){
                float2 e = cmul(ET[i], EH[j]);
                float va = Ak[c*27 + i*9 + j*3 + k];
                float vb = Bk[c*27 + i*9 + j*3 + k];
                aA.x = fmaf(va, e.x, aA.x); aA.y = fmaf(va, e.y, aA.y);
                aB.x = fmaf(vb, e.x, aB.x); aB.y = fmaf(vb, e.y, aB.y);
            }
        }
        vA[k] = aA; vB[k] = aB;
    }
    float2 sA = cadd(vA[0], vA[2]), dA = csub(vA[0], vA[2]);
    float2 sB = cadd(vB[0], vB[2]), dB = csub(vB[0], vB[2]);
    int idx = (t*64 + h)*64 + c;
    g_G2m[idx] = make_ulonglong2(PK2(vA[1].x, vA[1].y), PK2(vB[1].x, vB[1].y));
    g_G2s[idx] = make_ulonglong2(PK2(sA.x, sA.y),       PK2(sB.x, sB.y));
    g_G2d[idx] = make_ulonglong2(PK2(dA.y, -dA.x),      PK2(dB.y, -dB.x));
}

// ---------------------------------------------------------------------------
// Pass G: gates (sigmoid / softplus matvec) -> g_G {fgt, gt}, fp32 exact.
// Block = 256 threads = 4 w x 64 c; grid = B*H*(W/4) = 2048.
// Proven R6 staging + scalar matvec; high occupancy (no FFT state here).
// ---------------------------------------------------------------------------
__global__ void __launch_bounds__(256) gate_kernel(
    const float* __restrict__ x,
    const float* __restrict__ fb,  const float* __restrict__ fs,
    const float* __restrict__ ibv, const float* __restrict__ isc,
    const float* __restrict__ dW,  const float* __restrict__ db)
{
    __shared__ __align__(16) float pool[4096 + 64*68];   // sx 16KB + sWT 17KB
    float* sx  = pool;                 // [p*1024 + t*64 + c]
    float* sWT = pool + 4096;          // [c*68 + g]

    int tid = threadIdx.x;
    int c = tid & 63;
    int p = tid >> 6;
    int bi = blockIdx.x;
    int b  = bi >> 10;              // 1024 = Hh * (Ww/4)
    int h  = (bi >> 4) & 63;
    int w4 = bi & 15;
    int w  = w4*4 + p;

    // delta_W is [c2][d] row-major; store transposed sWT[d][c2]
#pragma unroll
    for(int k=0;k<16;k++){
        int i = tid + k*256;
        sWT[(i & 63)*68 + (i >> 6)] = dW[i];
    }
    // x tile: contiguous 1 KB per t across the 256 threads
    size_t xbase = (size_t)b*(Tt*Hh*Ww*Cc) + (size_t)h*(Ww*Cc) + (size_t)(w4*4)*Cc;
#pragma unroll
    for(int t=0;t<16;t++){
        float v = x[xbase + (size_t)t*(Hh*Ww*Cc) + tid];
        sx[(tid>>6)*1024 + t*64 + (tid&63)] = v;
    }
    __syncthreads();

    // delta[t][c] = softplus( sum_c2 x[t][c2] * W[c2][c] + db[c] )
    float dot[16];
    float dbc = db[c];
#pragma unroll
    for(int t=0;t<16;t++) dot[t] = dbc;
#pragma unroll
    for(int g=0; g<16; g++){
        float4 wv = *(const float4*)&sWT[c*68 + g*4];
#pragma unroll
        for(int t=0;t<16;t++){
            float4 xv = *(const float4*)&sx[p*1024 + t*64 + g*4];
            dot[t] = fmaf(xv.x, wv.x,
                     fmaf(xv.y, wv.y,
                     fmaf(xv.z, wv.z,
                     fmaf(xv.w, wv.w, dot[t]))));
        }
    }

    // gates -> g_G[b,t,h,w,c] (same layout as g_Y; coalesced STG.64 per t)
    size_t gbase = (size_t)b*(Tt*Hh*Ww*Cc) + (size_t)h*(Ww*Cc) + (size_t)w*Cc + c;
    float fbc = fb[c], fsc = fs[c], ibc = ibv[c], iscv = isc[c];
#pragma unroll
    for(int t=0;t<16;t++){
        float xv  = sx[p*1024 + t*64 + c];
        float fgt = __fdividef(1.f, 1.f + __expf(-(fbc + fsc*xv)));
        float igt = __fdividef(1.f, 1.f + __expf(-(ibc + iscv*xv)));
        float d   = dot[t];
        float spv = fmaxf(d, 0.f) + __logf(1.f + __expf(-fabsf(d)));
        g_G[gbase + (size_t)t*(Hh*Ww*Cc)] = make_float2(fgt, igt * spv);
    }
}

// ---------------------------------------------------------------------------
// Pass 1: forward FFT along W (length 64 = 8x8), real input -> g_Y complex.
// ---------------------------------------------------------------------------
__global__ void __launch_bounds__(512) fftW_fwd_kernel(const float* __restrict__ x){
    __shared__ float2 sh[8][8][64];     // [n1][k2][c]
    int c = threadIdx.x & 63;
    int r = threadIdx.x >> 6;
    size_t line = blockIdx.x;           // (b*T+t)*H + h
    const float* xp = x + line*(size_t)(Ww*Cc) + c;
    float2 v[8], o[8];
#pragma unroll
    for(int n2=0;n2<8;n2++) v[n2] = make_float2(xp[(r + 8*n2)*Cc], 0.f);
    dft8<-1>(v, o);
    float s_, c_;
    sincospif(-(float)r/32.0f, &s_, &c_);
    float2 wr = make_float2(c_, s_);
    float2 wcur = make_float2(1.f, 0.f);
#pragma unroll
    for(int k2=0;k2<8;k2++){
        sh[r][k2][c] = cmul(o[k2], wcur);
        wcur = cmul(wcur, wr);
    }
    __syncthreads();
#pragma unroll
    for(int n1=0;n1<8;n1++) v[n1] = sh[n1][r][c];
    dft8<-1>(v, o);
    float2* yp = g_Y + line*(size_t)(Ww*Cc) + c;
#pragma unroll
    for(int k1=0;k1<8;k1++) yp[(r + 8*k1)*Cc] = o[k1];
}

// ---------------------------------------------------------------------------
// Passes 2/4: FFT along H (length 64), complex, in-place in g_Y.
// ---------------------------------------------------------------------------
template<int SIGN>
__global__ void __launch_bounds__(512) fftH_kernel(){
    __shared__ float2 sh[8][8][64];
    int c = threadIdx.x & 63;
    int r = threadIdx.x >> 6;
    int line = blockIdx.x;              // (b*T+t)*W + w
    int bt = line >> 6;
    int w  = line & 63;
    float2* yp = g_Y + (size_t)bt*(Hh*Ww*Cc) + (size_t)w*Cc + c;
    float2 v[8], o[8];
#pragma unroll
    for(int n2=0;n2<8;n2++) v[n2] = yp[(size_t)(r + 8*n2)*(Ww*Cc)];
    dft8<SIGN>(v, o);
    float s_, c_;
    sincospif((float)SIGN*(float)r/32.0f, &s_, &c_);
    float2 wr = make_float2(c_, s_);
    float2 wcur = make_float2(1.f, 0.f);
#pragma unroll
    for(int k2=0;k2<8;k2++){
        sh[r][k2][c] = cmul(o[k2], wcur);
        wcur = cmul(wcur, wr);
    }
    __syncthreads();
#pragma unroll
    for(int n1=0;n1<8;n1++) v[n1] = sh[n1][r][c];
    dft8<SIGN>(v, o);
#pragma unroll
    for(int k1=0;k1<8;k1++) yp[(size_t)(r + 8*k1)*(Ww*Cc)] = o[k1];
}

// ---------------------------------------------------------------------------
// Pass 3: forward FFT16(T) + A_f/B_f synthesis + scan + inverse FFT16(T).
// No shared memory, no matvec — gates come from g_G. Block = 256 = 4w x 64c.
// ---------------------------------------------------------------------------
__global__ void __launch_bounds__(256) scan2_kernel(){
    int tid = threadIdx.x;
    int c = tid & 63;
    int p = tid >> 6;
    int bi = blockIdx.x;
    int b  = bi >> 10;              // 1024 = Hh * (Ww/4)
    int h  = (bi >> 4) & 63;
    int w4 = bi & 15;
    int w  = w4*4 + p;

    const size_t plane = (size_t)Hh*Ww*Cc;
    size_t ybase = (size_t)b*(Tt*plane) + (size_t)h*(Ww*Cc) + (size_t)w*Cc + c;

    // load T-line of (H,W)-transformed data; forward FFT along T in place
    float2 v[16];
#pragma unroll
    for(int t=0;t<16;t++) v[t] = g_Y[ybase + (size_t)t*plane];
    fft16_fwd_ip<-1>(v);     // slot 4q+j = bin q+4j

    // E = exp(-2pi i w/64); packed synthesis with pre-swapped diff tables:
    // Af = FMA2(dsw, ey2, FMA2(s, ex2, m))
    float ey, ex;
    sincospif(-(float)w/32.0f, &ey, &ex);
    ull ex2 = PK2(ex, ex), ey2 = PK2(ey, ey);

    float2 hp = make_float2(0.f, 0.f);
#pragma unroll
    for(int t=0;t<16;t++){
        const int sl = 4*(t&3) + (t>>2);     // digit-swapped slot of bin t
        float2 gv = g_G[ybase + (size_t)t*plane];   // {fgt, gt} coalesced LDG.64

        int gi = (t*64 + h)*64 + c;
        ulonglong2 m2 = g_G2m[gi];           // {mA, mB}  coalesced LDG.128
        ulonglong2 s2 = g_G2s[gi];           // {sA, sB}
        ulonglong2 d2 = g_G2d[gi];           // {dAsw, dBsw}
        float2 Af = UPK2(FMA2v(d2.x, ey2, FMA2v(s2.x, ex2, m2.x)));
        float2 Bf = UPK2(FMA2v(d2.y, ey2, FMA2v(s2.y, ex2, m2.y)));

        float2 at = make_float2(gv.x*Af.x, gv.x*Af.y);
        float2 bt = cmul(Bf, v[sl]);
        bt.x *= gv.y; bt.y *= gv.y;
        hp = cadd(cmul(at, hp), bt);          // h[t] = a*h[t-1] + b
        v[sl] = hp;
    }

    fft16_inv_ip<1>(v);                        // digit-swapped in -> natural out
#pragma unroll
    for(int t=0;t<16;t++){
        g_Y[ybase + (size_t)t*plane] = v[t];
    }
}

// ---------------------------------------------------------------------------
// Pass 5: inverse FFT along W, write real part * 1/(T*H*W) to output.
// ---------------------------------------------------------------------------
__global__ void __launch_bounds__(512) ifftW_real_kernel(float* __restrict__ out){
    __shared__ float2 sh[8][8][64];
    int c = threadIdx.x & 63;
    int r = threadIdx.x >> 6;
    size_t line = blockIdx.x;
    const float2* yp = g_Y + line*(size_t)(Ww*Cc) + c;
    float2 v[8], o[8];
#pragma unroll
    for(int n2=0;n2<8;n2++) v[n2] = yp[(size_t)(r + 8*n2)*Cc];
    dft8<1>(v, o);
    float s_, c_;
    sincospif((float)r/32.0f, &s_, &c_);
    float2 wr = make_float2(c_, s_);
    float2 wcur = make_float2(1.f, 0.f);
#pragma unroll
    for(int k2=0;k2<8;k2++){
        sh[r][k2][c] = cmul(o[k2], wcur);
        wcur = cmul(wcur, wr);
    }
    __syncthreads();
#pragma unroll
    for(int n1=0;n1<8;n1++) v[n1] = sh[n1][r][c];
    dft8<1>(v, o);
    float* op = out + line*(size_t)(Ww*Cc) + c;
    const float sc = 1.0f/65536.0f;          // 1/(T*H*W)
#pragma unroll
    for(int k1=0;k1<8;k1++) op[(r + 8*k1)*Cc] = o[k1].x * sc;
}

// ---------------------------------------------------------------------------
extern "C" void kernel_launch(void* const* d_in, const int* in_sizes, int n_in,
                              void* d_out, int out_size){
    const float* x   = (const float*)d_in[0];
    const float* Ak  = (const float*)d_in[1];
    const float* Bk  = (const float*)d_in[2];
    const float* fb  = (const float*)d_in[3];
    const float* fs  = (const float*)d_in[4];
    const float* ib  = (const float*)d_in[5];
    const float* isc = (const float*)d_in[6];
    const float* dW  = (const float*)d_in[7];
    const float* db  = (const float*)d_in[8];
    float* out = (float*)d_out;

    build_g2_kernel<<<Tt*Hh, 64>>>(Ak, Bk);
    gate_kernel<<<Bb*Hh*(Ww/4), 256>>>(x, fb, fs, ib, isc, dW, db);
    fftW_fwd_kernel<<<Bb*Tt*Hh, 512>>>(x);
    fftH_kernel<-1><<<Bb*Tt*Ww, 512>>>();
    scan2_kernel<<<Bb*Hh*(Ww/4), 256>>>();
    fftH_kernel<1><<<Bb*Tt*Ww, 512>>>();
    ifftW_real_kernel<<<Bb*Tt*Hh, 512>>>(out);
}

// round 12
// speedup vs baseline: 1.4392x; 1.3116x over previous
#include <cuda_runtime.h>
#include <math.h>

#define Bb 2
#define Tt 16
#define Hh 64
#define Ww 64
#define Cc 64

typedef unsigned long long ull;

// Scratch (static device globals: allowed; no cudaMalloc anywhere)
__device__ float2 g_Y[Bb*Tt*Hh*Ww*Cc];      // 67 MB working complex field
// Pair-packed kernel-DFT tables, 16B per (t,h,c) record -> coalesced LDG.128:
//   g_G2m = {mA, mB}, g_G2s = {sA, sB}, g_G2d = {dAsw, dBsw}
// where dXsw = (d.y, -d.x) pre-swapped for FFMA2 synthesis.
__device__ __align__(16) ulonglong2 g_G2m[Tt*Hh*Cc];
__device__ __align__(16) ulonglong2 g_G2s[Tt*Hh*Cc];
__device__ __align__(16) ulonglong2 g_G2d[Tt*Hh*Cc];

// ---------------- f32x2 packed helpers (sm_103a FFMA2 path) ----------------
__device__ __forceinline__ ull PK2(float x, float y){
    ull r; asm("mov.b64 %0, {%1,%2};" : "=l"(r) : "f"(x), "f"(y)); return r;
}
__device__ __forceinline__ float2 UPK2(ull p){
    float x, y; asm("mov.b64 {%0,%1}, %2;" : "=f"(x), "=f"(y) : "l"(p));
    return make_float2(x, y);
}
__device__ __forceinline__ ull FMA2v(ull a, ull b, ull c){
    ull r; asm("fma.rn.f32x2 %0, %1, %2, %3;" : "=l"(r) : "l"(a), "l"(b), "l"(c));
    return r;
}

__device__ __forceinline__ float2 cmul(float2 a, float2 b){
    return make_float2(fmaf(a.x, b.x, -a.y*b.y), fmaf(a.x, b.y, a.y*b.x));
}
__device__ __forceinline__ float2 cadd(float2 a, float2 b){
    return make_float2(a.x + b.x, a.y + b.y);
}
__device__ __forceinline__ float2 csub(float2 a, float2 b){
    return make_float2(a.x - b.x, a.y - b.y);
}

// exp(S * 2*pi*i * m / 16) as compile-time constants
#define C16_1 0.92387953251128675613f
#define C16_2 0.70710678118654752440f
#define C16_3 0.38268343236508977173f
__device__ __forceinline__ float2 w16c(int m, float S){
    switch(m){
        default: return make_float2( 1.f, 0.f);
        case 1:  return make_float2( C16_1,  S*C16_3);
        case 2:  return make_float2( C16_2,  S*C16_2);
        case 3:  return make_float2( C16_3,  S*C16_1);
        case 4:  return make_float2( 0.f,    S);
        case 5:  return make_float2(-C16_3,  S*C16_1);
        case 6:  return make_float2(-C16_2,  S*C16_2);
        case 7:  return make_float2(-C16_1,  S*C16_3);
        case 8:  return make_float2(-1.f,    0.f);
        case 9:  return make_float2(-C16_1, -S*C16_3);
    }
}
__device__ __forceinline__ float2 cmulW(float2 a, int m, float S){
    if(m == 0) return a;
    return cmul(a, w16c(m, S));
}

// 4-point butterfly, in place. SIGN=-1 forward, +1 inverse.
template<int SIGN>
__device__ __forceinline__ void b4(float2& x0, float2& x1, float2& x2, float2& x3){
    const float S = (float)SIGN;
    float2 e=cadd(x0,x2), f=csub(x0,x2);
    float2 g=cadd(x1,x3), h=csub(x1,x3);
    float2 ih=make_float2(-S*h.y, S*h.x);     // S*i*h
    x0=cadd(e,g); x1=cadd(f,ih); x2=csub(e,g); x3=csub(f,ih);
}

// In-place DIF radix-4 FFT16, natural input -> digit-swapped output:
// slot m = 4q+j holds bin k = q+4j.  SIGN=-1 (forward).
template<int SIGN>
__device__ __forceinline__ void fft16_fwd_ip(float2* v){
    const float S = (float)SIGN;
#pragma unroll
    for(int i=0;i<4;i++){
        b4<SIGN>(v[i], v[i+4], v[i+8], v[i+12]);
        v[i+4]  = cmulW(v[i+4],    i, S);
        v[i+8]  = cmulW(v[i+8],  2*i, S);
        v[i+12] = cmulW(v[i+12], 3*i, S);
    }
#pragma unroll
    for(int q=0;q<4;q++) b4<SIGN>(v[4*q], v[4*q+1], v[4*q+2], v[4*q+3]);
}

// In-place DIT radix-4 IFFT16, digit-swapped input -> natural output.
template<int SIGN>
__device__ __forceinline__ void fft16_inv_ip(float2* v){
    const float S = (float)SIGN;
#pragma unroll
    for(int q=0;q<4;q++){
        b4<SIGN>(v[4*q], v[4*q+1], v[4*q+2], v[4*q+3]);
        v[4*q+1] = cmulW(v[4*q+1],   q, S);
        v[4*q+2] = cmulW(v[4*q+2], 2*q, S);
        v[4*q+3] = cmulW(v[4*q+3], 3*q, S);
    }
#pragma unroll
    for(int i=0;i<4;i++) b4<SIGN>(v[i], v[i+4], v[i+8], v[i+12]);
}

// In-place radix-2 DIF FFT8, natural input AND natural output
// (bit-reversal folded into compile-time register indexing).
// SIGN=-1 forward, +1 inverse (unscaled). ~2 cmul + 3 i-mult + 24 add/sub.
template<int SIGN>
__device__ __forceinline__ void fft8(float2* v){
    const float S = (float)SIGN;
    const float R = 0.70710678118654752440f;
    // stage 1: u[n]=v[n]+v[n+4]; l[n]=(v[n]-v[n+4])*W8^n,  W8 = exp(S*2pi i/8)
    float2 u0=cadd(v[0],v[4]), u1=cadd(v[1],v[5]);
    float2 u2=cadd(v[2],v[6]), u3=cadd(v[3],v[7]);
    float2 l0=csub(v[0],v[4]);
    float2 l1=cmul(csub(v[1],v[5]), make_float2(R, S*R));
    float2 l2t=csub(v[2],v[6]);
    float2 l2=make_float2(-S*l2t.y, S*l2t.x);              // * (0, S)
    float2 l3=cmul(csub(v[3],v[7]), make_float2(-R, S*R));
    // stage 2+3: FFT4 on u -> even bins; FFT4 on l -> odd bins
    float2 p0=cadd(u0,u2), p1=cadd(u1,u3);
    float2 q0=csub(u0,u2);
    float2 q1t=csub(u1,u3);
    float2 q1=make_float2(-S*q1t.y, S*q1t.x);
    v[0]=cadd(p0,p1); v[4]=csub(p0,p1);                     // bins 0, 4
    v[2]=cadd(q0,q1); v[6]=csub(q0,q1);                     // bins 2, 6
    float2 r0=cadd(l0,l2), r1=cadd(l1,l3);
    float2 s0=csub(l0,l2);
    float2 s1t=csub(l1,l3);
    float2 s1=make_float2(-S*s1t.y, S*s1t.x);
    v[1]=cadd(r0,r1); v[5]=csub(r0,r1);                     // bins 1, 5
    v[3]=cadd(s0,s1); v[7]=csub(s0,s1);                     // bins 3, 7
}

// ---------------------------------------------------------------------------
// Pass 0: separable DFT of the 3x3x3 kernels over (T,H) axes -> pair tables.
// ---------------------------------------------------------------------------
__global__ void build_g2_kernel(const float* __restrict__ Ak,
                                const float* __restrict__ Bk){
    int c = threadIdx.x;            // 64
    int t = blockIdx.x >> 6;        // grid = Tt*Hh = 1024
    int h = blockIdx.x & 63;
    float s_, c_;
    float2 ET[3], EH[3];
    sincospif(2.0f*(float)t/16.0f, &s_, &c_);
    ET[0] = make_float2(c_,  s_);
    ET[1] = make_float2(1.f, 0.f);
    ET[2] = make_float2(c_, -s_);
    sincospif(2.0f*(float)h/64.0f, &s_, &c_);
    EH[0] = make_float2(c_,  s_);
    EH[1] = make_float2(1.f, 0.f);
    EH[2] = make_float2(c_, -s_);
    float2 vA[3], vB[3];
#pragma unroll
    for(int k=0;k<3;k++){
        float2 aA = make_float2(0.f,0.f), aB = make_float2(0.f,0.f);
#pragma unroll
        for(int i=0;i<3;i++){
#pragma unroll
            for(int j=0;j<3;j++){
                float2 e = cmul(ET[i], EH[j]);
                float va = Ak[c*27 + i*9 + j*3 + k];
                float vb = Bk[c*27 + i*9 + j*3 + k];
                aA.x = fmaf(va, e.x, aA.x); aA.y = fmaf(va, e.y, aA.y);
                aB.x = fmaf(vb, e.x, aB.x); aB.y = fmaf(vb, e.y, aB.y);
            }
        }
        vA[k] = aA; vB[k] = aB;
    }
    float2 sA = cadd(vA[0], vA[2]), dA = csub(vA[0], vA[2]);
    float2 sB = cadd(vB[0], vB[2]), dB = csub(vB[0], vB[2]);
    int idx = (t*64 + h)*64 + c;
    g_G2m[idx] = make_ulonglong2(PK2(vA[1].x, vA[1].y), PK2(vB[1].x, vB[1].y));
    g_G2s[idx] = make_ulonglong2(PK2(sA.x, sA.y),       PK2(sB.x, sB.y));
    g_G2d[idx] = make_ulonglong2(PK2(dA.y, -dA.x),      PK2(dB.y, -dB.x));
}

// ---------------------------------------------------------------------------
// Pass 1: forward FFT along W (length 64 = 8x8), real input -> g_Y complex.
// ---------------------------------------------------------------------------
__global__ void __launch_bounds__(512) fftW_fwd_kernel(const float* __restrict__ x){
    __shared__ float2 sh[8][8][64];     // [n1][k2][c]
    int c = threadIdx.x & 63;
    int r = threadIdx.x >> 6;
    size_t line = blockIdx.x;           // (b*T+t)*H + h
    const float* xp = x + line*(size_t)(Ww*Cc) + c;
    float2 v[8];
#pragma unroll
    for(int n2=0;n2<8;n2++) v[n2] = make_float2(xp[(r + 8*n2)*Cc], 0.f);
    fft8<-1>(v);
    float s_, c_;
    sincospif(-(float)r/32.0f, &s_, &c_);
    float2 wr = make_float2(c_, s_);
    float2 wcur = make_float2(1.f, 0.f);
#pragma unroll
    for(int k2=0;k2<8;k2++){
        sh[r][k2][c] = cmul(v[k2], wcur);
        wcur = cmul(wcur, wr);
    }
    __syncthreads();
#pragma unroll
    for(int n1=0;n1<8;n1++) v[n1] = sh[n1][r][c];
    fft8<-1>(v);
    float2* yp = g_Y + line*(size_t)(Ww*Cc) + c;
#pragma unroll
    for(int k1=0;k1<8;k1++) yp[(r + 8*k1)*Cc] = v[k1];
}

// ---------------------------------------------------------------------------
// Passes 2/4: FFT along H (length 64), complex, in-place in g_Y.
// ---------------------------------------------------------------------------
template<int SIGN>
__global__ void __launch_bounds__(512) fftH_kernel(){
    __shared__ float2 sh[8][8][64];
    int c = threadIdx.x & 63;
    int r = threadIdx.x >> 6;
    int line = blockIdx.x;              // (b*T+t)*W + w
    int bt = line >> 6;
    int w  = line & 63;
    float2* yp = g_Y + (size_t)bt*(Hh*Ww*Cc) + (size_t)w*Cc + c;
    float2 v[8];
#pragma unroll
    for(int n2=0;n2<8;n2++) v[n2] = yp[(size_t)(r + 8*n2)*(Ww*Cc)];
    fft8<SIGN>(v);
    float s_, c_;
    sincospif((float)SIGN*(float)r/32.0f, &s_, &c_);
    float2 wr = make_float2(c_, s_);
    float2 wcur = make_float2(1.f, 0.f);
#pragma unroll
    for(int k2=0;k2<8;k2++){
        sh[r][k2][c] = cmul(v[k2], wcur);
        wcur = cmul(wcur, wr);
    }
    __syncthreads();
#pragma unroll
    for(int n1=0;n1<8;n1++) v[n1] = sh[n1][r][c];
    fft8<SIGN>(v);
#pragma unroll
    for(int k1=0;k1<8;k1++) yp[(size_t)(r + 8*k1)*(Ww*Cc)] = v[k1];
}

// ---------------------------------------------------------------------------
// Pass 3 (fused): forward FFT16(T) + gates + A_f/B_f synthesis + scan +
// inverse FFT16(T). Block = 256 threads = 4 w x 64 c; grid = B*H*(W/4).
// Shared pool (48 KB static):
//   [0 .. 16384)      sx[p][t][c] floats (x tile)
//   [16384 .. 33792)  sWT[c][68] floats (delta_W transposed)
//   [16384 .. 49152)  overlay after matvec barrier: sg2[p][t][c] float2 {fgt,gt}
// ---------------------------------------------------------------------------
__global__ void __launch_bounds__(256, 3) scan_kernel(
    const float* __restrict__ x,
    const float* __restrict__ fb,  const float* __restrict__ fs,
    const float* __restrict__ ibv, const float* __restrict__ isc,
    const float* __restrict__ dW,  const float* __restrict__ db)
{
    __shared__ __align__(16) char pool[49152];
    float*  sx  = (float*)pool;                 // [p*1024 + t*64 + c]
    float*  sWT = (float*)(pool + 16384);       // [c*68 + g]
    float2* sg2 = (float2*)(pool + 16384);      // overlay: [p*1024 + t*64 + c]

    int tid = threadIdx.x;
    int c = tid & 63;
    int p = tid >> 6;
    int bi = blockIdx.x;
    int b  = bi >> 10;              // 1024 = Hh * (Ww/4)
    int h  = (bi >> 4) & 63;
    int w4 = bi & 15;
    int w  = w4*4 + p;

    // delta_W is [c2][d] row-major; store transposed sWT[d][c2]
#pragma unroll
    for(int k=0;k<16;k++){
        int i = tid + k*256;
        sWT[(i & 63)*68 + (i >> 6)] = dW[i];
    }
    // x tile: contiguous 1 KB per t across the 256 threads
    size_t xbase = (size_t)b*(Tt*Hh*Ww*Cc) + (size_t)h*(Ww*Cc) + (size_t)(w4*4)*Cc;
#pragma unroll
    for(int t=0;t<16;t++){
        float v = x[xbase + (size_t)t*(Hh*Ww*Cc) + tid];
        sx[(tid>>6)*1024 + t*64 + (tid&63)] = v;
    }
    __syncthreads();

    // delta[t][c] = softplus( sum_c2 x[t][c2] * W[c2][c] + db[c] )
    float dot[16];
    float dbc = db[c];
#pragma unroll
    for(int t=0;t<16;t++) dot[t] = dbc;
#pragma unroll
    for(int g=0; g<16; g++){
        float4 wv = *(const float4*)&sWT[c*68 + g*4];
#pragma unroll
        for(int t=0;t<16;t++){
            float4 xv = *(const float4*)&sx[p*1024 + t*64 + g*4];
            dot[t] = fmaf(xv.x, wv.x,
                     fmaf(xv.y, wv.y,
                     fmaf(xv.z, wv.z,
                     fmaf(xv.w, wv.w, dot[t]))));
        }
    }
    __syncthreads();   // matvec reads of sWT done before sg2 overlay is written

    // Gate precompute into packed float2 {fgt, gt}
    {
        float fbc = fb[c], fsc = fs[c], ibc = ibv[c], iscv = isc[c];
#pragma unroll
        for(int t=0;t<16;t++){
            int sl_ix = p*1024 + t*64 + c;
            float xv  = sx[sl_ix];
            float fgt = __fdividef(1.f, 1.f + __expf(-(fbc + fsc*xv)));
            float igt = __fdividef(1.f, 1.f + __expf(-(ibc + iscv*xv)));
            float d   = dot[t];
            float spv = fmaxf(d, 0.f) + __logf(1.f + __expf(-fabsf(d)));
            sg2[sl_ix] = make_float2(fgt, igt * spv);
        }
    }

    // load T-line of (H,W)-transformed data; forward FFT along T in place
    size_t ybase = (size_t)b*(Tt*Hh*Ww*Cc) + (size_t)h*(Ww*Cc) + (size_t)w*Cc + c;
    float2 v[16];
#pragma unroll
    for(int t=0;t<16;t++) v[t] = g_Y[ybase + (size_t)t*(Hh*Ww*Cc)];
    fft16_fwd_ip<-1>(v);     // slot 4q+j = bin q+4j

    // E = exp(-2pi i w/64); packed synthesis with pre-swapped diff tables:
    // Af = FMA2(dsw, ey2, FMA2(s, ex2, m))
    float ey, ex;
    sincospif(-(float)w/32.0f, &ey, &ex);
    ull ex2 = PK2(ex, ex), ey2 = PK2(ey, ey);

    float2 hp = make_float2(0.f, 0.f);
#pragma unroll
    for(int t=0;t<16;t++){
        const int sl = 4*(t&3) + (t>>2);     // digit-swapped slot of bin t
        float2 gv = sg2[p*1024 + t*64 + c];  // {fgt, gt}

        int gi = (t*64 + h)*64 + c;
        ulonglong2 m2 = g_G2m[gi];           // {mA, mB}  coalesced LDG.128
        ulonglong2 s2 = g_G2s[gi];           // {sA, sB}
        ulonglong2 d2 = g_G2d[gi];           // {dAsw, dBsw}
        float2 Af = UPK2(FMA2v(d2.x, ey2, FMA2v(s2.x, ex2, m2.x)));
        float2 Bf = UPK2(FMA2v(d2.y, ey2, FMA2v(s2.y, ex2, m2.y)));

        float2 at = make_float2(gv.x*Af.x, gv.x*Af.y);
        float2 bt = cmul(Bf, v[sl]);
        bt.x *= gv.y; bt.y *= gv.y;
        hp = cadd(cmul(at, hp), bt);          // h[t] = a*h[t-1] + b
        v[sl] = hp;
    }

    fft16_inv_ip<1>(v);                        // digit-swapped in -> natural out
#pragma unroll
    for(int t=0;t<16;t++){
        g_Y[ybase + (size_t)t*(Hh*Ww*Cc)] = v[t];
    }
}

// ---------------------------------------------------------------------------
// Pass 5: inverse FFT along W, write real part * 1/(T*H*W) to output.
// ---------------------------------------------------------------------------
__global__ void __launch_bounds__(512) ifftW_real_kernel(float* __restrict__ out){
    __shared__ float2 sh[8][8][64];
    int c = threadIdx.x & 63;
    int r = threadIdx.x >> 6;
    size_t line = blockIdx.x;
    const float2* yp = g_Y + line*(size_t)(Ww*Cc) + c;
    float2 v[8];
#pragma unroll
    for(int n2=0;n2<8;n2++) v[n2] = yp[(size_t)(r + 8*n2)*Cc];
    fft8<1>(v);
    float s_, c_;
    sincospif((float)r/32.0f, &s_, &c_);
    float2 wr = make_float2(c_, s_);
    float2 wcur = make_float2(1.f, 0.f);
#pragma unroll
    for(int k2=0;k2<8;k2++){
        sh[r][k2][c] = cmul(v[k2], wcur);
        wcur = cmul(wcur, wr);
    }
    __syncthreads();
#pragma unroll
    for(int n1=0;n1<8;n1++) v[n1] = sh[n1][r][c];
    fft8<1>(v);
    float* op = out + line*(size_t)(Ww*Cc) + c;
    const float sc = 1.0f/65536.0f;          // 1/(T*H*W)
#pragma unroll
    for(int k1=0;k1<8;k1++) op[(r + 8*k1)*Cc] = v[k1].x * sc;
}

// ---------------------------------------------------------------------------
extern "C" void kernel_launch(void* const* d_in, const int* in_sizes, int n_in,
                              void* d_out, int out_size){
    const float* x   = (const float*)d_in[0];
    const float* Ak  = (const float*)d_in[1];
    const float* Bk  = (const float*)d_in[2];
    const float* fb  = (const float*)d_in[3];
    const float* fs  = (const float*)d_in[4];
    const float* ib  = (const float*)d_in[5];
    const float* isc = (const float*)d_in[6];
    const float* dW  = (const float*)d_in[7];
    const float* db  = (const float*)d_in[8];
    float* out = (float*)d_out;

    build_g2_kernel<<<Tt*Hh, 64>>>(Ak, Bk);
    fftW_fwd_kernel<<<Bb*Tt*Hh, 512>>>(x);
    fftH_kernel<-1><<<Bb*Tt*Ww, 512>>>();
    scan_kernel<<<Bb*Hh*(Ww/4), 256>>>(x, fb, fs, ib, isc, dW, db);
    fftH_kernel<1><<<Bb*Tt*Ww, 512>>>();
    ifftW_real_kernel<<<Bb*Tt*Hh, 512>>>(out);
}

// round 15
// speedup vs baseline: 1.5411x; 1.0708x over previous
#include <cuda_runtime.h>
#include <math.h>
#include <stdint.h>

#define Bb 2
#define Tt 16
#define Hh 64
#define Ww 64
#define Cc 64

typedef unsigned long long ull;

// Scratch (static device globals: allowed; no cudaMalloc anywhere)
__device__ float2 g_Y[Bb*Tt*Hh*Ww*Cc];      // 67 MB working complex field
// Pair-packed kernel-DFT tables, 16B per (t,h,c) record -> coalesced LDG.128:
//   g_G2m = {mA, mB}, g_G2s = {sA, sB}, g_G2d = {dAsw, dBsw}
// where dXsw = (d.y, -d.x) pre-swapped for FFMA2 synthesis.
__device__ __align__(16) ulonglong2 g_G2m[Tt*Hh*Cc];
__device__ __align__(16) ulonglong2 g_G2s[Tt*Hh*Cc];
__device__ __align__(16) ulonglong2 g_G2d[Tt*Hh*Cc];

// ---------------- f32x2 packed helpers (sm_103a FFMA2 path) ----------------
__device__ __forceinline__ ull PK2(float x, float y){
    ull r; asm("mov.b64 %0, {%1,%2};" : "=l"(r) : "f"(x), "f"(y)); return r;
}
__device__ __forceinline__ float2 UPK2(ull p){
    float x, y; asm("mov.b64 {%0,%1}, %2;" : "=f"(x), "=f"(y) : "l"(p));
    return make_float2(x, y);
}
__device__ __forceinline__ ull FMA2v(ull a, ull b, ull c){
    ull r; asm("fma.rn.f32x2 %0, %1, %2, %3;" : "=l"(r) : "l"(a), "l"(b), "l"(c));
    return r;
}

__device__ __forceinline__ float2 cmul(float2 a, float2 b){
    return make_float2(fmaf(a.x, b.x, -a.y*b.y), fmaf(a.x, b.y, a.y*b.x));
}
__device__ __forceinline__ float2 cadd(float2 a, float2 b){
    return make_float2(a.x + b.x, a.y + b.y);
}
__device__ __forceinline__ float2 csub(float2 a, float2 b){
    return make_float2(a.x - b.x, a.y - b.y);
}

// exp(S * 2*pi*i * m / 16) as compile-time constants
#define C16_1 0.92387953251128675613f
#define C16_2 0.70710678118654752440f
#define C16_3 0.38268343236508977173f
__device__ __forceinline__ float2 w16c(int m, float S){
    switch(m){
        default: return make_float2( 1.f, 0.f);
        case 1:  return make_float2( C16_1,  S*C16_3);
        case 2:  return make_float2( C16_2,  S*C16_2);
        case 3:  return make_float2( C16_3,  S*C16_1);
        case 4:  return make_float2( 0.f,    S);
        case 5:  return make_float2(-C16_3,  S*C16_1);
        case 6:  return make_float2(-C16_2,  S*C16_2);
        case 7:  return make_float2(-C16_1,  S*C16_3);
        case 8:  return make_float2(-1.f,    0.f);
        case 9:  return make_float2(-C16_1, -S*C16_3);
    }
}
__device__ __forceinline__ float2 cmulW(float2 a, int m, float S){
    if(m == 0) return a;
    return cmul(a, w16c(m, S));
}

// 4-point butterfly, in place. SIGN=-1 forward, +1 inverse.
template<int SIGN>
__device__ __forceinline__ void b4(float2& x0, float2& x1, float2& x2, float2& x3){
    const float S = (float)SIGN;
    float2 e=cadd(x0,x2), f=csub(x0,x2);
    float2 g=cadd(x1,x3), h=csub(x1,x3);
    float2 ih=make_float2(-S*h.y, S*h.x);     // S*i*h
    x0=cadd(e,g); x1=cadd(f,ih); x2=csub(e,g); x3=csub(f,ih);
}

// In-place DIF radix-4 FFT16, natural input -> digit-swapped output:
// slot m = 4q+j holds bin k = q+4j.  SIGN=-1 (forward).
template<int SIGN>
__device__ __forceinline__ void fft16_fwd_ip(float2* v){
    const float S = (float)SIGN;
#pragma unroll
    for(int i=0;i<4;i++){
        b4<SIGN>(v[i], v[i+4], v[i+8], v[i+12]);
        v[i+4]  = cmulW(v[i+4],    i, S);
        v[i+8]  = cmulW(v[i+8],  2*i, S);
        v[i+12] = cmulW(v[i+12], 3*i, S);
    }
#pragma unroll
    for(int q=0;q<4;q++) b4<SIGN>(v[4*q], v[4*q+1], v[4*q+2], v[4*q+3]);
}

// In-place DIT radix-4 IFFT16, digit-swapped input -> natural output.
template<int SIGN>
__device__ __forceinline__ void fft16_inv_ip(float2* v){
    const float S = (float)SIGN;
#pragma unroll
    for(int q=0;q<4;q++){
        b4<SIGN>(v[4*q], v[4*q+1], v[4*q+2], v[4*q+3]);
        v[4*q+1] = cmulW(v[4*q+1],   q, S);
        v[4*q+2] = cmulW(v[4*q+2], 2*q, S);
        v[4*q+3] = cmulW(v[4*q+3], 3*q, S);
    }
#pragma unroll
    for(int i=0;i<4;i++) b4<SIGN>(v[i], v[i+4], v[i+8], v[i+12]);
}

// In-place radix-2 DIF FFT8, natural input AND natural output
// (bit-reversal folded into compile-time register indexing).
// SIGN=-1 forward, +1 inverse (unscaled). ~2 cmul + 3 i-mult + 24 add/sub.
template<int SIGN>
__device__ __forceinline__ void fft8(float2* v){
    const float S = (float)SIGN;
    const float R = 0.70710678118654752440f;
    float2 u0=cadd(v[0],v[4]), u1=cadd(v[1],v[5]);
    float2 u2=cadd(v[2],v[6]), u3=cadd(v[3],v[7]);
    float2 l0=csub(v[0],v[4]);
    float2 l1=cmul(csub(v[1],v[5]), make_float2(R, S*R));
    float2 l2t=csub(v[2],v[6]);
    float2 l2=make_float2(-S*l2t.y, S*l2t.x);              // * (0, S)
    float2 l3=cmul(csub(v[3],v[7]), make_float2(-R, S*R));
    float2 p0=cadd(u0,u2), p1=cadd(u1,u3);
    float2 q0=csub(u0,u2);
    float2 q1t=csub(u1,u3);
    float2 q1=make_float2(-S*q1t.y, S*q1t.x);
    v[0]=cadd(p0,p1); v[4]=csub(p0,p1);
    v[2]=cadd(q0,q1); v[6]=csub(q0,q1);
    float2 r0=cadd(l0,l2), r1=cadd(l1,l3);
    float2 s0=csub(l0,l2);
    float2 s1t=csub(l1,l3);
    float2 s1=make_float2(-S*s1t.y, S*s1t.x);
    v[1]=cadd(r0,r1); v[5]=csub(r0,r1);
    v[3]=cadd(s0,s1); v[7]=csub(s0,s1);
}

// ---------------------------------------------------------------------------
// Pass 0: separable DFT of the 3x3x3 kernels over (T,H) axes -> pair tables.
// ---------------------------------------------------------------------------
__global__ void build_g2_kernel(const float* __restrict__ Ak,
                                const float* __restrict__ Bk){
    int c = threadIdx.x;            // 64
    int t = blockIdx.x >> 6;        // grid = Tt*Hh = 1024
    int h = blockIdx.x & 63;
    float s_, c_;
    float2 ET[3], EH[3];
    sincospif(2.0f*(float)t/16.0f, &s_, &c_);
    ET[0] = make_float2(c_,  s_);
    ET[1] = make_float2(1.f, 0.f);
    ET[2] = make_float2(c_, -s_);
    sincospif(2.0f*(float)h/64.0f, &s_, &c_);
    EH[0] = make_float2(c_,  s_);
    EH[1] = make_float2(1.f, 0.f);
    EH[2] = make_float2(c_, -s_);
    float2 vA[3], vB[3];
#pragma unroll
    for(int k=0;k<3;k++){
        float2 aA = make_float2(0.f,0.f), aB = make_float2(0.f,0.f);
#pragma unroll
        for(int i=0;i<3;i++){
#pragma unroll
            for(int j=0;j<3;j++){
                float2 e = cmul(ET[i], EH[j]);
                float va = Ak[c*27 + i*9 + j*3 + k];
                float vb = Bk[c*27 + i*9 + j*3 + k];
                aA.x = fmaf(va, e.x, aA.x); aA.y = fmaf(va, e.y, aA.y);
                aB.x = fmaf(vb, e.x, aB.x); aB.y = fmaf(vb, e.y, aB.y);
            }
        }
        vA[k] = aA; vB[k] = aB;
    }
    float2 sA = cadd(vA[0], vA[2]), dA = csub(vA[0], vA[2]);
    float2 sB = cadd(vB[0], vB[2]), dB = csub(vB[0], vB[2]);
    int idx = (t*64 + h)*64 + c;
    g_G2m[idx] = make_ulonglong2(PK2(vA[1].x, vA[1].y), PK2(vB[1].x, vB[1].y));
    g_G2s[idx] = make_ulonglong2(PK2(sA.x, sA.y),       PK2(sB.x, sB.y));
    g_G2d[idx] = make_ulonglong2(PK2(dA.y, -dA.x),      PK2(dB.y, -dB.x));
}

// ---------------------------------------------------------------------------
// Pass 1: forward FFT along W (length 64 = 8x8), real input -> g_Y complex.
// ---------------------------------------------------------------------------
__global__ void __launch_bounds__(512) fftW_fwd_kernel(const float* __restrict__ x){
    __shared__ float2 sh[8][8][64];     // [n1][k2][c]
    int c = threadIdx.x & 63;
    int r = threadIdx.x >> 6;
    size_t line = blockIdx.x;           // (b*T+t)*H + h
    const float* xp = x + line*(size_t)(Ww*Cc) + c;
    float2 v[8];
#pragma unroll
    for(int n2=0;n2<8;n2++) v[n2] = make_float2(xp[(r + 8*n2)*Cc], 0.f);
    fft8<-1>(v);
    float s_, c_;
    sincospif(-(float)r/32.0f, &s_, &c_);
    float2 wr = make_float2(c_, s_);
    float2 wcur = make_float2(1.f, 0.f);
#pragma unroll
    for(int k2=0;k2<8;k2++){
        sh[r][k2][c] = cmul(v[k2], wcur);
        wcur = cmul(wcur, wr);
    }
    __syncthreads();
#pragma unroll
    for(int n1=0;n1<8;n1++) v[n1] = sh[n1][r][c];
    fft8<-1>(v);
    float2* yp = g_Y + line*(size_t)(Ww*Cc) + c;
#pragma unroll
    for(int k1=0;k1<8;k1++) yp[(r + 8*k1)*Cc] = v[k1];
}

// ---------------------------------------------------------------------------
// Passes 2/4: FFT along H (length 64), complex, in-place in g_Y.
// ---------------------------------------------------------------------------
template<int SIGN>
__global__ void __launch_bounds__(512) fftH_kernel(){
    __shared__ float2 sh[8][8][64];
    int c = threadIdx.x & 63;
    int r = threadIdx.x >> 6;
    int line = blockIdx.x;              // (b*T+t)*W + w
    int bt = line >> 6;
    int w  = line & 63;
    float2* yp = g_Y + (size_t)bt*(Hh*Ww*Cc) + (size_t)w*Cc + c;
    float2 v[8];
#pragma unroll
    for(int n2=0;n2<8;n2++) v[n2] = yp[(size_t)(r + 8*n2)*(Ww*Cc)];
    fft8<SIGN>(v);
    float s_, c_;
    sincospif((float)SIGN*(float)r/32.0f, &s_, &c_);
    float2 wr = make_float2(c_, s_);
    float2 wcur = make_float2(1.f, 0.f);
#pragma unroll
    for(int k2=0;k2<8;k2++){
        sh[r][k2][c] = cmul(v[k2], wcur);
        wcur = cmul(wcur, wr);
    }
    __syncthreads();
#pragma unroll
    for(int n1=0;n1<8;n1++) v[n1] = sh[n1][r][c];
    fft8<SIGN>(v);
#pragma unroll
    for(int k1=0;k1<8;k1++) yp[(size_t)(r + 8*k1)*(Ww*Cc)] = v[k1];
}

// ---------------------------------------------------------------------------
// Pass 3 (fused): forward FFT16(T) + gates + A_f/B_f synthesis + scan +
// inverse FFT16(T). Block = 256 threads = 4 w x 64 c; grid = B*H*(W/4).
// Dynamic shared pool (81 KB):
//   [0 .. 16384)        sx[p][t][c] floats (x tile)        } phase 1
//   [16384 .. 33792)    sWT[c][68] floats                  } phase 1
//   [0 .. 32768)        overlay AFTER barrier: sg2[p][t][c] float2 {fgt,gt}
//                       (gates are computed into registers BEFORE the barrier;
//                        the overlay is only written after all sx reads done)
//   [33792 .. 82944)    st_m / st_s / st_d: block's 48 KB table slice,
//                       prefetched via cp.async overlapped with the matvec.
// ---------------------------------------------------------------------------
__global__ void __launch_bounds__(256, 2) scan_kernel(
    const float* __restrict__ x,
    const float* __restrict__ fb,  const float* __restrict__ fs,
    const float* __restrict__ ibv, const float* __restrict__ isc,
    const float* __restrict__ dW,  const float* __restrict__ db)
{
    extern __shared__ __align__(16) char pool[];
    float*      sx   = (float*)pool;                 // [p*1024 + t*64 + c]
    float*      sWT  = (float*)(pool + 16384);       // [c*68 + g]
    float2*     sg2  = (float2*)pool;                // overlay [p*1024+t*64+c]
    ulonglong2* st_m = (ulonglong2*)(pool + 33792);  // [t*64 + c]
    ulonglong2* st_s = (ulonglong2*)(pool + 33792 + 16384);
    ulonglong2* st_d = (ulonglong2*)(pool + 33792 + 32768);

    int tid = threadIdx.x;
    int c = tid & 63;
    int p = tid >> 6;
    int bi = blockIdx.x;
    int b  = bi >> 10;              // 1024 = Hh * (Ww/4)
    int h  = (bi >> 4) & 63;
    int w4 = bi & 15;
    int w  = w4*4 + p;

    // ---- cp.async: prefetch this block's 48 KB table slice (all t, all c) ----
    {
        unsigned int sb;
        asm("{ .reg .u64 t0; cvta.to.shared.u64 t0, %1; cvt.u32.u64 %0, t0; }"
            : "=r"(sb) : "l"(pool));
        unsigned int dm = sb + 33792u;
        unsigned int ds = dm + 16384u;
        unsigned int dd = ds + 16384u;
#pragma unroll
        for(int k=0;k<4;k++){
            int l = tid + k*256;                 // 0..1023 = t*64 + c2
            int gsrc = ((l >> 6)*64 + h)*64 + (l & 63);
            unsigned int off = (unsigned int)l*16u;
            asm volatile("cp.async.cg.shared.global [%0], [%1], 16;"
                         :: "r"(dm + off), "l"(g_G2m + gsrc));
            asm volatile("cp.async.cg.shared.global [%0], [%1], 16;"
                         :: "r"(ds + off), "l"(g_G2s + gsrc));
            asm volatile("cp.async.cg.shared.global [%0], [%1], 16;"
                         :: "r"(dd + off), "l"(g_G2d + gsrc));
        }
        asm volatile("cp.async.commit_group;" ::: "memory");
    }

    // delta_W is [c2][d] row-major; store transposed sWT[d][c2]
#pragma unroll
    for(int k=0;k<16;k++){
        int i = tid + k*256;
        sWT[(i & 63)*68 + (i >> 6)] = dW[i];
    }
    // x tile: contiguous 1 KB per t across the 256 threads
    size_t xbase = (size_t)b*(Tt*Hh*Ww*Cc) + (size_t)h*(Ww*Cc) + (size_t)(w4*4)*Cc;
#pragma unroll
    for(int t=0;t<16;t++){
        float v = x[xbase + (size_t)t*(Hh*Ww*Cc) + tid];
        sx[(tid>>6)*1024 + t*64 + (tid&63)] = v;
    }
    __syncthreads();

    // delta[t][c] = softplus( sum_c2 x[t][c2] * W[c2][c] + db[c] )
    float dot[16];
    float dbc = db[c];
#pragma unroll
    for(int t=0;t<16;t++) dot[t] = dbc;
#pragma unroll
    for(int g=0; g<16; g++){
        float4 wv = *(const float4*)&sWT[c*68 + g*4];
#pragma unroll
        for(int t=0;t<16;t++){
            float4 xv = *(const float4*)&sx[p*1024 + t*64 + g*4];
            dot[t] = fmaf(xv.x, wv.x,
                     fmaf(xv.y, wv.y,
                     fmaf(xv.z, wv.z,
                     fmaf(xv.w, wv.w, dot[t]))));
        }
    }

    // Gates into REGISTERS while sx is still valid (own-slot reads only).
    float gf[16], gg[16];
    {
        float fbc = fb[c], fsc = fs[c], ibc = ibv[c], iscv = isc[c];
#pragma unroll
        for(int t=0;t<16;t++){
            float xv  = sx[p*1024 + t*64 + c];
            float fgt = __fdividef(1.f, 1.f + __expf(-(fbc + fsc*xv)));
            float igt = __fdividef(1.f, 1.f + __expf(-(ibc + iscv*xv)));
            float d   = dot[t];
            float spv = fmaxf(d, 0.f) + __logf(1.f + __expf(-fabsf(d)));
            gf[t] = fgt;
            gg[t] = igt * spv;
        }
    }
    __syncthreads();   // ALL sx/sWT reads complete -> safe to overlay sg2
#pragma unroll
    for(int t=0;t<16;t++){
        sg2[p*1024 + t*64 + c] = make_float2(gf[t], gg[t]);
    }

    // Tables must be fully landed (all threads') before the scan loop.
    asm volatile("cp.async.wait_group 0;" ::: "memory");
    __syncthreads();

    // load T-line of (H,W)-transformed data; forward FFT along T in place
    size_t ybase = (size_t)b*(Tt*Hh*Ww*Cc) + (size_t)h*(Ww*Cc) + (size_t)w*Cc + c;
    float2 v[16];
#pragma unroll
    for(int t=0;t<16;t++) v[t] = g_Y[ybase + (size_t)t*(Hh*Ww*Cc)];
    fft16_fwd_ip<-1>(v);     // slot 4q+j = bin q+4j

    // E = exp(-2pi i w/64); packed synthesis with pre-swapped diff tables:
    // Af = FMA2(dsw, ey2, FMA2(s, ex2, m))
    float ey, ex;
    sincospif(-(float)w/32.0f, &ey, &ex);
    ull ex2 = PK2(ex, ex), ey2 = PK2(ey, ey);

    float2 hp = make_float2(0.f, 0.f);
#pragma unroll
    for(int t=0;t<16;t++){
        const int sl = 4*(t&3) + (t>>2);     // digit-swapped slot of bin t
        float2 gv = sg2[p*1024 + t*64 + c];  // {fgt, gt}  LDS.64

        int si = t*64 + c;
        ulonglong2 m2 = st_m[si];            // LDS.128 conflict-free
        ulonglong2 s2 = st_s[si];
        ulonglong2 d2 = st_d[si];
        float2 Af = UPK2(FMA2v(d2.x, ey2, FMA2v(s2.x, ex2, m2.x)));
        float2 Bf = UPK2(FMA2v(d2.y, ey2, FMA2v(s2.y, ex2, m2.y)));

        float2 at = make_float2(gv.x*Af.x, gv.x*Af.y);
        float2 bt = cmul(Bf, v[sl]);
        bt.x *= gv.y; bt.y *= gv.y;
        hp = cadd(cmul(at, hp), bt);          // h[t] = a*h[t-1] + b
        v[sl] = hp;
    }

    fft16_inv_ip<1>(v);                        // digit-swapped in -> natural out
#pragma unroll
    for(int t=0;t<16;t++){
        g_Y[ybase + (size_t)t*(Hh*Ww*Cc)] = v[t];
    }
}

// ---------------------------------------------------------------------------
// Pass 5: inverse FFT along W, write real part * 1/(T*H*W) to output.
// ---------------------------------------------------------------------------
__global__ void __launch_bounds__(512) ifftW_real_kernel(float* __restrict__ out){
    __shared__ float2 sh[8][8][64];
    int c = threadIdx.x & 63;
    int r = threadIdx.x >> 6;
    size_t line = blockIdx.x;
    const float2* yp = g_Y + line*(size_t)(Ww*Cc) + c;
    float2 v[8];
#pragma unroll
    for(int n2=0;n2<8;n2++) v[n2] = yp[(size_t)(r + 8*n2)*Cc];
    fft8<1>(v);
    float s_, c_;
    sincospif((float)r/32.0f, &s_, &c_);
    float2 wr = make_float2(c_, s_);
    float2 wcur = make_float2(1.f, 0.f);
#pragma unroll
    for(int k2=0;k2<8;k2++){
        sh[r][k2][c] = cmul(v[k2], wcur);
        wcur = cmul(wcur, wr);
    }
    __syncthreads();
#pragma unroll
    for(int n1=0;n1<8;n1++) v[n1] = sh[n1][r][c];
    fft8<1>(v);
    float* op = out + line*(size_t)(Ww*Cc) + c;
    const float sc = 1.0f/65536.0f;          // 1/(T*H*W)
#pragma unroll
    for(int k1=0;k1<8;k1++) op[(r + 8*k1)*Cc] = v[k1].x * sc;
}

// ---------------------------------------------------------------------------
extern "C" void kernel_launch(void* const* d_in, const int* in_sizes, int n_in,
                              void* d_out, int out_size){
    const float* x   = (const float*)d_in[0];
    const float* Ak  = (const float*)d_in[1];
    const float* Bk  = (const float*)d_in[2];
    const float* fb  = (const float*)d_in[3];
    const float* fs  = (const float*)d_in[4];
    const float* ib  = (const float*)d_in[5];
    const float* isc = (const float*)d_in[6];
    const float* dW  = (const float*)d_in[7];
    const float* db  = (const float*)d_in[8];
    float* out = (float*)d_out;

    const int SCAN_SMEM = 33792 + 49152;   // 82944 B
    cudaFuncSetAttribute(scan_kernel,
                         cudaFuncAttributeMaxDynamicSharedMemorySize, SCAN_SMEM);

    build_g2_kernel<<<Tt*Hh, 64>>>(Ak, Bk);
    fftW_fwd_kernel<<<Bb*Tt*Hh, 512>>>(x);
    fftH_kernel<-1><<<Bb*Tt*Ww, 512>>>();
    scan_kernel<<<Bb*Hh*(Ww/4), 256, SCAN_SMEM>>>(x, fb, fs, ib, isc, dW, db);
    fftH_kernel<1><<<Bb*Tt*Ww, 512>>>();
    ifftW_real_kernel<<<Bb*Tt*Hh, 512>>>(out);
}